// round 11
// baseline (speedup 1.0000x reference)
#include <cuda_runtime.h>
#include <cuda_bf16.h>
#include <math.h>

#define Nn 100000
#define Ee 1600000
#define Gg 64

// ---------------- packed f32x2 helpers ----------------
#define PACK2(out, a, b) \
    asm("mov.b64 %0, {%1, %2};" : "=l"(out) : "f"(a), "f"(b))
#define FMA2(acc, a, b) \
    asm("fma.rn.f32x2 %0, %1, %2, %0;" : "+l"(acc) : "l"(a), "l"(b))

// ---------------- device scratch (static, no runtime allocation) ----------------
__device__ int   g_cnt[Nn];
__device__ int   g_rowptr[Nn + 1];
__device__ int   g_cursor[Nn];
__device__ int   g_cols[Ee];
__device__ float g_dis[Nn];
__device__ float g_bufA[Nn * 64];
__device__ float g_bufB[Nn * 64];
__device__ float g_stats[3 * 128];      // per layer: [0..H) sum, [H..2H) sumsq
__device__ int   g_bsum[256];           // scan partials
__device__ float g_pool[Gg * 33];       // per graph: sum[16], max[16], count
__device__ int   g_pooldone;            // pool completion counter

// ---------------- small utility kernels (round-5 skeleton, measured best) -------
__global__ void k_zero() {
    int i = blockIdx.x * 256 + threadIdx.x;
    if (i < Nn) g_cnt[i] = 0;
    if (i < 3 * 128) g_stats[i] = 0.f;
    if (i == 0) g_pooldone = 0;
}
__global__ void k_hist(const int4* __restrict__ dst4) {
    int e = blockIdx.x * 256 + threadIdx.x;
    if (e < Ee / 4) {
        int4 d = dst4[e];
        atomicAdd(&g_cnt[d.x], 1);
        atomicAdd(&g_cnt[d.y], 1);
        atomicAdd(&g_cnt[d.z], 1);
        atomicAdd(&g_cnt[d.w], 1);
    }
}
__global__ void k_dis() {
    int i = blockIdx.x * 256 + threadIdx.x;
    if (i < Nn) g_dis[i] = rsqrtf((float)(g_cnt[i] + 1));
}

#define SCAN_NB 196   // 196 * 512 = 100352 >= Nn

__global__ void k_scan1() {
    __shared__ int sh[512];
    int t = threadIdx.x, idx = blockIdx.x * 512 + t;
    sh[t] = (idx < Nn) ? g_cnt[idx] : 0;
    __syncthreads();
    for (int off = 256; off > 0; off >>= 1) {
        if (t < off) sh[t] += sh[t + off];
        __syncthreads();
    }
    if (t == 0) g_bsum[blockIdx.x] = sh[0];
}
__global__ void k_scan2() {
    __shared__ int sh[256];
    int t = threadIdx.x;
    int v = (t < SCAN_NB) ? g_bsum[t] : 0;
    sh[t] = v;
    __syncthreads();
    for (int off = 1; off < 256; off <<= 1) {
        int add = (t >= off) ? sh[t - off] : 0;
        __syncthreads();
        sh[t] += add;
        __syncthreads();
    }
    if (t < SCAN_NB) g_bsum[t] = sh[t] - v;   // exclusive
    if (t == 0) g_rowptr[Nn] = Ee;
}
__global__ void k_scan3() {
    __shared__ int sh[512];
    int t = threadIdx.x, idx = blockIdx.x * 512 + t;
    int v = (idx < Nn) ? g_cnt[idx] : 0;
    sh[t] = v;
    __syncthreads();
    for (int off = 1; off < 512; off <<= 1) {
        int add = (t >= off) ? sh[t - off] : 0;
        __syncthreads();
        sh[t] += add;
        __syncthreads();
    }
    if (idx < Nn) {
        int ex = g_bsum[blockIdx.x] + sh[t] - v;
        g_rowptr[idx] = ex;
        g_cursor[idx] = ex;
    }
}
__global__ void k_fill(const int4* __restrict__ src4, const int4* __restrict__ dst4) {
    int e = blockIdx.x * 256 + threadIdx.x;
    if (e < Ee / 4) {
        int4 s = src4[e];
        int4 d = dst4[e];
        g_cols[atomicAdd(&g_cursor[d.x], 1)] = s.x;
        g_cols[atomicAdd(&g_cursor[d.y], 1)] = s.y;
        g_cols[atomicAdd(&g_cursor[d.z], 1)] = s.z;
        g_cols[atomicAdd(&g_cursor[d.w], 1)] = s.w;
    }
}

// ---------------- GEMM (round-5 body: fp32, transposed-x, packed f32x2) ---------
template <int K, int H, bool NORM>
__global__ void __launch_bounds__(128, 4) k_gemm(const float* __restrict__ h,
                                                 const float* __restrict__ W,
                                                 const float* __restrict__ stats,
                                                 const float* __restrict__ gamma,
                                                 const float* __restrict__ beta,
                                                 float* __restrict__ out) {
    constexpr int C = H / 4;
    __shared__ float Wsm[16 * H];
    __shared__ float xt[16][128];
    __shared__ float nsc[K], nsh[K];
    const int tid = threadIdx.x;
    const int base = blockIdx.x * 128;
    const int n0 = (tid & 31) * 4;
    const int cg = tid >> 5;
    const int cbase = cg * C;

    if (NORM) {
        for (int c = tid; c < K; c += 128) {
            float m = stats[c] * (1.0f / Nn);
            float var = stats[K + c] * (1.0f / Nn) - m * m;
            float rstd = rsqrtf(var + 1e-5f);
            float sc = rstd * gamma[c];
            nsc[c] = sc;
            nsh[c] = beta[c] - m * sc;
        }
        __syncthreads();
    }

    unsigned long long acc2[4][C / 2];
#pragma unroll
    for (int t = 0; t < 4; t++)
#pragma unroll
        for (int j = 0; j < C / 2; j++) acc2[t][j] = 0ull;

    const int myrow = base + tid;

    for (int kc = 0; kc < K; kc += 16) {
        {
            const float4* Wg = reinterpret_cast<const float4*>(W + kc * H);
            float4* Ws = reinterpret_cast<float4*>(Wsm);
#pragma unroll
            for (int i = tid; i < 16 * H / 4; i += 128) Ws[i] = Wg[i];
        }
#pragma unroll
        for (int q = 0; q < 4; q++) {
            float4 v = make_float4(0.f, 0.f, 0.f, 0.f);
            if (myrow < Nn)
                v = *reinterpret_cast<const float4*>(h + (size_t)myrow * K + kc + q * 4);
            if (NORM) {
                int cb = kc + q * 4;
                v.x = v.x * nsc[cb + 0] + nsh[cb + 0]; v.x = v.x > 0.f ? v.x : 0.1f * v.x;
                v.y = v.y * nsc[cb + 1] + nsh[cb + 1]; v.y = v.y > 0.f ? v.y : 0.1f * v.y;
                v.z = v.z * nsc[cb + 2] + nsh[cb + 2]; v.z = v.z > 0.f ? v.z : 0.1f * v.z;
                v.w = v.w * nsc[cb + 3] + nsh[cb + 3]; v.w = v.w > 0.f ? v.w : 0.1f * v.w;
            }
            xt[q * 4 + 0][tid] = v.x;
            xt[q * 4 + 1][tid] = v.y;
            xt[q * 4 + 2][tid] = v.z;
            xt[q * 4 + 3][tid] = v.w;
        }
        __syncthreads();
#pragma unroll
        for (int kk = 0; kk < 16; kk++) {
            float4 xv = *reinterpret_cast<const float4*>(&xt[kk][n0]);
            unsigned long long x0, x1, x2, x3;
            PACK2(x0, xv.x, xv.x);
            PACK2(x1, xv.y, xv.y);
            PACK2(x2, xv.z, xv.z);
            PACK2(x3, xv.w, xv.w);
            const ulonglong2* w2 =
                reinterpret_cast<const ulonglong2*>(&Wsm[kk * H + cbase]);
#pragma unroll
            for (int j = 0; j < C / 4; j++) {
                ulonglong2 w = w2[j];
                FMA2(acc2[0][2 * j + 0], x0, w.x);
                FMA2(acc2[0][2 * j + 1], x0, w.y);
                FMA2(acc2[1][2 * j + 0], x1, w.x);
                FMA2(acc2[1][2 * j + 1], x1, w.y);
                FMA2(acc2[2][2 * j + 0], x2, w.x);
                FMA2(acc2[2][2 * j + 1], x2, w.y);
                FMA2(acc2[3][2 * j + 0], x3, w.x);
                FMA2(acc2[3][2 * j + 1], x3, w.y);
            }
        }
        __syncthreads();
    }

#pragma unroll
    for (int t = 0; t < 4; t++) {
        int node = base + n0 + t;
        if (node < Nn) {
            float dn = g_dis[node];
            const float* a = reinterpret_cast<const float*>(acc2[t]);
            float* o = out + (size_t)node * H + cbase;
#pragma unroll
            for (int j = 0; j < C / 4; j++) {
                float4 r;
                r.x = a[4 * j + 0] * dn;
                r.y = a[4 * j + 1] * dn;
                r.z = a[4 * j + 2] * dn;
                r.w = a[4 * j + 3] * dn;
                *reinterpret_cast<float4*>(o + 4 * j) = r;
            }
        }
    }
}

// ---------------- gather: channel-pair lanes, multi-edge warps ------------------
// pre[i] = dis[i]*(hws[i] + sum_{e:dst=i} hws[src]) + b ; fused BN stats.
// Lane owns channel pair c0 = 2*(lane % (H/2)); group grp = lane/(H/2) processes
// every GPW-th edge in parallel (GPW = 64/H edges per warp-instruction).
// 8-edge-deep unroll keeps >=8 independent LDG.64 in flight per warp.
template <int H>
__global__ void __launch_bounds__(256) k_gather(const float* __restrict__ hws,
                                                const float* __restrict__ b,
                                                float* __restrict__ pre,
                                                float* __restrict__ stats) {
    constexpr int LPN = H / 2;        // lanes per edge
    constexpr int GPW = 32 / LPN;     // edges per warp-instruction
    const int lane = threadIdx.x & 31;
    const int grp = lane / LPN;
    const int cp = lane % LPN;
    const int c0 = 2 * cp;
    const int warp = (blockIdx.x * blockDim.x + threadIdx.x) >> 5;
    const int nwarps = (gridDim.x * blockDim.x) >> 5;

    const float2 bia = *reinterpret_cast<const float2*>(b + c0);
    float sx = 0.f, sy = 0.f, qx = 0.f, qy = 0.f;

    for (int node = warp; node < Nn; node += nwarps) {
        const int r0 = g_rowptr[node], r1 = g_rowptr[node + 1];
        float ax0 = 0.f, ay0 = 0.f, ax1 = 0.f, ay1 = 0.f;
        float ax2 = 0.f, ay2 = 0.f, ax3 = 0.f, ay3 = 0.f;
        int p = r0 + grp;
        // 8-step body: 8 independent row loads in flight
        for (; p + 7 * GPW < r1; p += 8 * GPW) {
            int s0 = g_cols[p + 0 * GPW];
            int s1 = g_cols[p + 1 * GPW];
            int s2 = g_cols[p + 2 * GPW];
            int s3 = g_cols[p + 3 * GPW];
            int s4 = g_cols[p + 4 * GPW];
            int s5 = g_cols[p + 5 * GPW];
            int s6 = g_cols[p + 6 * GPW];
            int s7 = g_cols[p + 7 * GPW];
            float2 v0 = *reinterpret_cast<const float2*>(hws + (size_t)s0 * H + c0);
            float2 v1 = *reinterpret_cast<const float2*>(hws + (size_t)s1 * H + c0);
            float2 v2 = *reinterpret_cast<const float2*>(hws + (size_t)s2 * H + c0);
            float2 v3 = *reinterpret_cast<const float2*>(hws + (size_t)s3 * H + c0);
            float2 v4 = *reinterpret_cast<const float2*>(hws + (size_t)s4 * H + c0);
            float2 v5 = *reinterpret_cast<const float2*>(hws + (size_t)s5 * H + c0);
            float2 v6 = *reinterpret_cast<const float2*>(hws + (size_t)s6 * H + c0);
            float2 v7 = *reinterpret_cast<const float2*>(hws + (size_t)s7 * H + c0);
            ax0 += v0.x + v4.x; ay0 += v0.y + v4.y;
            ax1 += v1.x + v5.x; ay1 += v1.y + v5.y;
            ax2 += v2.x + v6.x; ay2 += v2.y + v6.y;
            ax3 += v3.x + v7.x; ay3 += v3.y + v7.y;
        }
        // tail (per-group strided)
        for (; p < r1; p += GPW) {
            int s = g_cols[p];
            float2 v = *reinterpret_cast<const float2*>(hws + (size_t)s * H + c0);
            ax0 += v.x; ay0 += v.y;
        }
        float ax = (ax0 + ax1) + (ax2 + ax3);
        float ay = (ay0 + ay1) + (ay2 + ay3);
        if (GPW > 1) {
#pragma unroll
            for (int off = LPN; off < 32; off <<= 1) {
                ax += __shfl_xor_sync(0xffffffffu, ax, off);
                ay += __shfl_xor_sync(0xffffffffu, ay, off);
            }
        }
        if (grp == 0) {
            float2 self = *reinterpret_cast<const float2*>(hws + (size_t)node * H + c0);
            float dn = g_dis[node];
            float vx = dn * (ax + self.x) + bia.x;
            float vy = dn * (ay + self.y) + bia.y;
            *reinterpret_cast<float2*>(pre + (size_t)node * H + c0) = make_float2(vx, vy);
            sx += vx; sy += vy;
            qx += vx * vx; qy += vy * vy;
        }
    }
    if (grp == 0) {
        atomicAdd(&stats[c0], sx);
        atomicAdd(&stats[c0 + 1], sy);
        atomicAdd(&stats[H + c0], qx);
        atomicAdd(&stats[H + c0 + 1], qy);
    }
}

// ---------------- pool + head fused (last pool block runs the head) -------------
__device__ __forceinline__ int lower_bound_batch(const int* __restrict__ batch, int g) {
    int lo = 0, hi = Nn;
    while (lo < hi) {
        int m = (lo + hi) >> 1;
        if (batch[m] < g) lo = m + 1; else hi = m;
    }
    return lo;
}

__global__ void k_poolhead(const float* __restrict__ x3, const int* __restrict__ batch,
                           const float* __restrict__ stats,
                           const float* __restrict__ gamma, const float* __restrict__ beta,
                           const float* __restrict__ attn_w, const float* __restrict__ attn_b,
                           const float* __restrict__ fc1_w, const float* __restrict__ fc1_b,
                           const float* __restrict__ fc2_w, const float* __restrict__ fc2_b,
                           const float* __restrict__ out_w, const float* __restrict__ out_b,
                           float* __restrict__ out) {
    __shared__ int ss, se, slast;
    __shared__ float ssum[256], smax[256];
    int g = blockIdx.x, t = threadIdx.x;
    if (t == 0) { ss = lower_bound_batch(batch, g); se = lower_bound_batch(batch, g + 1); }
    __syncthreads();
    int s = ss, e = se;
    int c = t & 15;
    float m = stats[c] * (1.0f / Nn);
    float var = stats[16 + c] * (1.0f / Nn) - m * m;
    float rstd = rsqrtf(var + 1e-5f);
    float sc = rstd * gamma[c];
    float sh = beta[c] - m * sc;

    float sum = 0.f, mx = -3.402823466e+38f;
    for (int r = s + (t >> 4); r < e; r += 16) {
        float v = x3[(size_t)r * 16 + c] * sc + sh;
        v = v > 0.f ? v : 0.1f * v;
        sum += v;
        mx = fmaxf(mx, v);
    }
    ssum[t] = sum; smax[t] = mx;
    __syncthreads();
    for (int off = 128; off >= 16; off >>= 1) {
        if (t < off) { ssum[t] += ssum[t + off]; smax[t] = fmaxf(smax[t], smax[t + off]); }
        __syncthreads();
    }
    if (t < 16) { g_pool[g * 33 + t] = ssum[t]; g_pool[g * 33 + 16 + t] = smax[t]; }
    if (t == 0) g_pool[g * 33 + 32] = (float)(e - s);

    __threadfence();
    __syncthreads();
    if (t == 0) slast = atomicAdd(&g_pooldone, 1);
    __syncthreads();
    if (slast != Gg - 1) return;
    __threadfence();

    if (t < Gg) {
        int gg = t;
        float sm2[16], mx2[16], mean[16];
        float cnt = __ldcg(&g_pool[gg * 33 + 32]);
        float inv = 1.0f / fmaxf(cnt, 1.0f);
#pragma unroll
        for (int k = 0; k < 16; k++) {
            sm2[k] = __ldcg(&g_pool[gg * 33 + k]);
            mx2[k] = __ldcg(&g_pool[gg * 33 + 16 + k]);
            mean[k] = sm2[k] * inv;
        }
        float z[3];
#pragma unroll
        for (int j = 0; j < 3; j++) z[j] = attn_b[j];
#pragma unroll
        for (int k = 0; k < 16; k++) {
#pragma unroll
            for (int j = 0; j < 3; j++) {
                z[j] += mean[k] * attn_w[k * 3 + j]
                      + mx2[k]  * attn_w[(16 + k) * 3 + j]
                      + sm2[k]  * attn_w[(32 + k) * 3 + j];
            }
        }
        float zm = fmaxf(z[0], fmaxf(z[1], z[2]));
        float e0 = expf(z[0] - zm), e1 = expf(z[1] - zm), e2 = expf(z[2] - zm);
        float is = 1.f / (e0 + e1 + e2);
        float a0 = e0 * is, a1 = e1 * is, a2 = e2 * is;
        float xg[16];
#pragma unroll
        for (int k = 0; k < 16; k++) xg[k] = a0 * mean[k] + a1 * mx2[k] + a2 * sm2[k];
        float y1[16];
#pragma unroll
        for (int j = 0; j < 16; j++) {
            float acc = fc1_b[j];
#pragma unroll
            for (int k = 0; k < 16; k++) acc += xg[k] * fc1_w[k * 16 + j];
            y1[j] = acc > 0.f ? acc : 0.1f * acc;
        }
        float y2[8];
#pragma unroll
        for (int j = 0; j < 8; j++) {
            float acc = fc2_b[j];
#pragma unroll
            for (int k = 0; k < 16; k++) acc += y1[k] * fc2_w[k * 8 + j];
            y2[j] = acc > 0.f ? acc : 0.1f * acc;
        }
        float o = out_b[0];
#pragma unroll
        for (int k = 0; k < 8; k++) o += y2[k] * out_w[k];
        out[gg] = 1.f / (1.f + expf(-o));
    }
}

// ---------------- host launch ----------------
extern "C" void kernel_launch(void* const* d_in, const int* in_sizes, int n_in,
                              void* d_out, int out_size) {
    const float* x      = (const float*)d_in[0];
    const float* W1     = (const float*)d_in[1];
    const float* b1     = (const float*)d_in[2];
    const float* W2     = (const float*)d_in[3];
    const float* b2     = (const float*)d_in[4];
    const float* W3     = (const float*)d_in[5];
    const float* b3     = (const float*)d_in[6];
    const float* g1     = (const float*)d_in[7];
    const float* be1    = (const float*)d_in[8];
    const float* g2     = (const float*)d_in[9];
    const float* be2    = (const float*)d_in[10];
    const float* g3     = (const float*)d_in[11];
    const float* be3    = (const float*)d_in[12];
    const float* attn_w = (const float*)d_in[13];
    const float* attn_b = (const float*)d_in[14];
    const float* fc1_w  = (const float*)d_in[15];
    const float* fc1_b  = (const float*)d_in[16];
    const float* fc2_w  = (const float*)d_in[17];
    const float* fc2_b  = (const float*)d_in[18];
    const float* out_w  = (const float*)d_in[19];
    const float* out_b  = (const float*)d_in[20];
    const int*   ei     = (const int*)d_in[21];
    const int*   batch  = (const int*)d_in[22];

    const int* src = ei;
    const int* dst = ei + Ee;
    float* out = (float*)d_out;

    void *pA = nullptr, *pB = nullptr, *pS = nullptr;
    cudaGetSymbolAddress(&pA, g_bufA);
    cudaGetSymbolAddress(&pB, g_bufB);
    cudaGetSymbolAddress(&pS, g_stats);
    float* bufA = (float*)pA;
    float* bufB = (float*)pB;
    float* st0 = (float*)pS;
    float* st1 = st0 + 128;
    float* st2 = st0 + 256;

    static cudaStream_t sB = nullptr;
    static cudaEvent_t evFork = nullptr, evJoin = nullptr;
    if (sB == nullptr) {
        cudaStreamCreateWithFlags(&sB, cudaStreamNonBlocking);
        cudaEventCreateWithFlags(&evFork, cudaEventDisableTiming);
        cudaEventCreateWithFlags(&evJoin, cudaEventDisableTiming);
    }

    const int gemm_grid = (Nn + 127) / 128;   // 782
    const int gather_grid = 1184;             // 148 SMs * 8 blocks

    // ---- prefix: degree + dis (round-5 skeleton) ----
    k_zero<<<(Nn + 255) / 256, 256>>>();
    k_hist<<<(Ee / 4 + 255) / 256, 256>>>((const int4*)dst);
    k_dis<<<(Nn + 255) / 256, 256>>>();
    cudaEventRecord(evFork, 0);

    // ---- branch B: GEMM1 (needs only dis), overlaps scan/fill ----
    cudaStreamWaitEvent(sB, evFork, 0);
    k_gemm<128, 64, false><<<gemm_grid, 128, 0, sB>>>(x, W1, nullptr, nullptr, nullptr, bufA);
    cudaEventRecord(evJoin, sB);

    // ---- branch A (main stream): CSR scan + fill ----
    k_scan1<<<SCAN_NB, 512>>>();
    k_scan2<<<1, 256>>>();
    k_scan3<<<SCAN_NB, 512>>>();
    k_fill<<<(Ee / 4 + 255) / 256, 256>>>((const int4*)src, (const int4*)dst);

    // ---- join: gather needs CSR + GEMM1 output ----
    cudaStreamWaitEvent(0, evJoin, 0);
    k_gather<64><<<gather_grid, 256>>>(bufA, b1, bufB, st0);

    // Layer 2: 64 -> 32 (BN1 + lrelu fused into GEMM load)
    k_gemm<64, 32, true><<<gemm_grid, 128>>>(bufB, W2, st0, g1, be1, bufA);
    k_gather<32><<<gather_grid, 256>>>(bufA, b2, bufB, st1);

    // Layer 3: 32 -> 16 (BN2 + lrelu fused into GEMM load)
    k_gemm<32, 16, true><<<gemm_grid, 128>>>(bufB, W3, st1, g2, be2, bufA);
    k_gather<16><<<gather_grid, 256>>>(bufA, b3, bufB, st2);

    // Pool (BN3 + lrelu fused) + head (fused)
    k_poolhead<<<Gg, 256>>>(bufB, batch, st2, g3, be3,
                            attn_w, attn_b, fc1_w, fc1_b, fc2_w, fc2_b,
                            out_w, out_b, out);
}

// round 12
// speedup vs baseline: 1.1547x; 1.1547x over previous
#include <cuda_runtime.h>
#include <cuda_bf16.h>
#include <math.h>

#define Nn 100000
#define Ee 1600000
#define Gg 64

// ---------------- packed f32x2 helpers ----------------
#define PACK2(out, a, b) \
    asm("mov.b64 %0, {%1, %2};" : "=l"(out) : "f"(a), "f"(b))
#define FMA2(acc, a, b) \
    asm("fma.rn.f32x2 %0, %1, %2, %0;" : "+l"(acc) : "l"(a), "l"(b))

// ---------------- device scratch (static, no runtime allocation) ----------------
__device__ int   g_cnt[Nn];
__device__ int   g_rowptr[Nn + 1];
__device__ int   g_cursor[Nn];
__device__ int   g_cols[Ee];
__device__ float g_dis[Nn];
__device__ float g_bufA[Nn * 64];
__device__ float g_bufB[Nn * 64];
__device__ float g_stats[3 * 128];      // per layer: [0..H) sum, [H..2H) sumsq
__device__ int   g_bsum[256];           // scan partials
__device__ float g_pool[Gg * 33];       // per graph: sum[16], max[16], count
__device__ int   g_pooldone;            // pool completion counter

// ---------------- small utility kernels (round-5 skeleton, measured best) -------
__global__ void k_zero() {
    int i = blockIdx.x * 256 + threadIdx.x;
    if (i < Nn) g_cnt[i] = 0;
    if (i < 3 * 128) g_stats[i] = 0.f;
    if (i == 0) g_pooldone = 0;
}
__global__ void k_hist(const int* __restrict__ dst) {
    int e = blockIdx.x * 256 + threadIdx.x;
    if (e < Ee) atomicAdd(&g_cnt[dst[e]], 1);
}
__global__ void k_dis() {
    int i = blockIdx.x * 256 + threadIdx.x;
    if (i < Nn) g_dis[i] = rsqrtf((float)(g_cnt[i] + 1));
}

#define SCAN_NB 196   // 196 * 512 = 100352 >= Nn

__global__ void k_scan1() {
    __shared__ int sh[512];
    int t = threadIdx.x, idx = blockIdx.x * 512 + t;
    sh[t] = (idx < Nn) ? g_cnt[idx] : 0;
    __syncthreads();
    for (int off = 256; off > 0; off >>= 1) {
        if (t < off) sh[t] += sh[t + off];
        __syncthreads();
    }
    if (t == 0) g_bsum[blockIdx.x] = sh[0];
}
__global__ void k_scan2() {
    __shared__ int sh[256];
    int t = threadIdx.x;
    int v = (t < SCAN_NB) ? g_bsum[t] : 0;
    sh[t] = v;
    __syncthreads();
    for (int off = 1; off < 256; off <<= 1) {
        int add = (t >= off) ? sh[t - off] : 0;
        __syncthreads();
        sh[t] += add;
        __syncthreads();
    }
    if (t < SCAN_NB) g_bsum[t] = sh[t] - v;   // exclusive
    if (t == 0) g_rowptr[Nn] = Ee;
}
__global__ void k_scan3() {
    __shared__ int sh[512];
    int t = threadIdx.x, idx = blockIdx.x * 512 + t;
    int v = (idx < Nn) ? g_cnt[idx] : 0;
    sh[t] = v;
    __syncthreads();
    for (int off = 1; off < 512; off <<= 1) {
        int add = (t >= off) ? sh[t - off] : 0;
        __syncthreads();
        sh[t] += add;
        __syncthreads();
    }
    if (idx < Nn) {
        int ex = g_bsum[blockIdx.x] + sh[t] - v;
        g_rowptr[idx] = ex;
        g_cursor[idx] = ex;
    }
}
__global__ void k_fill(const int* __restrict__ src, const int* __restrict__ dst) {
    int e = blockIdx.x * 256 + threadIdx.x;
    if (e < Ee) {
        int d = dst[e];
        int p = atomicAdd(&g_cursor[d], 1);
        g_cols[p] = src[e];
    }
}

// ---------------- GEMM (round-5 body: fp32, transposed-x, packed f32x2) ---------
template <int K, int H, bool NORM>
__global__ void __launch_bounds__(128, 4) k_gemm(const float* __restrict__ h,
                                                 const float* __restrict__ W,
                                                 const float* __restrict__ stats,
                                                 const float* __restrict__ gamma,
                                                 const float* __restrict__ beta,
                                                 float* __restrict__ out) {
    constexpr int C = H / 4;
    __shared__ float Wsm[16 * H];
    __shared__ float xt[16][128];
    __shared__ float nsc[K], nsh[K];
    const int tid = threadIdx.x;
    const int base = blockIdx.x * 128;
    const int n0 = (tid & 31) * 4;
    const int cg = tid >> 5;
    const int cbase = cg * C;

    if (NORM) {
        for (int c = tid; c < K; c += 128) {
            float m = stats[c] * (1.0f / Nn);
            float var = stats[K + c] * (1.0f / Nn) - m * m;
            float rstd = rsqrtf(var + 1e-5f);
            float sc = rstd * gamma[c];
            nsc[c] = sc;
            nsh[c] = beta[c] - m * sc;
        }
        __syncthreads();
    }

    unsigned long long acc2[4][C / 2];
#pragma unroll
    for (int t = 0; t < 4; t++)
#pragma unroll
        for (int j = 0; j < C / 2; j++) acc2[t][j] = 0ull;

    const int myrow = base + tid;

    for (int kc = 0; kc < K; kc += 16) {
        {
            const float4* Wg = reinterpret_cast<const float4*>(W + kc * H);
            float4* Ws = reinterpret_cast<float4*>(Wsm);
#pragma unroll
            for (int i = tid; i < 16 * H / 4; i += 128) Ws[i] = Wg[i];
        }
#pragma unroll
        for (int q = 0; q < 4; q++) {
            float4 v = make_float4(0.f, 0.f, 0.f, 0.f);
            if (myrow < Nn)
                v = *reinterpret_cast<const float4*>(h + (size_t)myrow * K + kc + q * 4);
            if (NORM) {
                int cb = kc + q * 4;
                v.x = v.x * nsc[cb + 0] + nsh[cb + 0]; v.x = v.x > 0.f ? v.x : 0.1f * v.x;
                v.y = v.y * nsc[cb + 1] + nsh[cb + 1]; v.y = v.y > 0.f ? v.y : 0.1f * v.y;
                v.z = v.z * nsc[cb + 2] + nsh[cb + 2]; v.z = v.z > 0.f ? v.z : 0.1f * v.z;
                v.w = v.w * nsc[cb + 3] + nsh[cb + 3]; v.w = v.w > 0.f ? v.w : 0.1f * v.w;
            }
            xt[q * 4 + 0][tid] = v.x;
            xt[q * 4 + 1][tid] = v.y;
            xt[q * 4 + 2][tid] = v.z;
            xt[q * 4 + 3][tid] = v.w;
        }
        __syncthreads();
#pragma unroll
        for (int kk = 0; kk < 16; kk++) {
            float4 xv = *reinterpret_cast<const float4*>(&xt[kk][n0]);
            unsigned long long x0, x1, x2, x3;
            PACK2(x0, xv.x, xv.x);
            PACK2(x1, xv.y, xv.y);
            PACK2(x2, xv.z, xv.z);
            PACK2(x3, xv.w, xv.w);
            const ulonglong2* w2 =
                reinterpret_cast<const ulonglong2*>(&Wsm[kk * H + cbase]);
#pragma unroll
            for (int j = 0; j < C / 4; j++) {
                ulonglong2 w = w2[j];
                FMA2(acc2[0][2 * j + 0], x0, w.x);
                FMA2(acc2[0][2 * j + 1], x0, w.y);
                FMA2(acc2[1][2 * j + 0], x1, w.x);
                FMA2(acc2[1][2 * j + 1], x1, w.y);
                FMA2(acc2[2][2 * j + 0], x2, w.x);
                FMA2(acc2[2][2 * j + 1], x2, w.y);
                FMA2(acc2[3][2 * j + 0], x3, w.x);
                FMA2(acc2[3][2 * j + 1], x3, w.y);
            }
        }
        __syncthreads();
    }

#pragma unroll
    for (int t = 0; t < 4; t++) {
        int node = base + n0 + t;
        if (node < Nn) {
            float dn = g_dis[node];
            const float* a = reinterpret_cast<const float*>(acc2[t]);
            float* o = out + (size_t)node * H + cbase;
#pragma unroll
            for (int j = 0; j < C / 4; j++) {
                float4 r;
                r.x = a[4 * j + 0] * dn;
                r.y = a[4 * j + 1] * dn;
                r.z = a[4 * j + 2] * dn;
                r.w = a[4 * j + 3] * dn;
                *reinterpret_cast<float4*>(o + 4 * j) = r;
            }
        }
    }
}

// ---------------- gather H=64: EXACT round-5 scalar body (measured 70.6us) ------
__global__ void __launch_bounds__(256) k_gather64(const float* __restrict__ hws,
                                                  const float* __restrict__ b,
                                                  float* __restrict__ pre,
                                                  float* __restrict__ stats) {
    const int lane = threadIdx.x & 31;
    const int warp = (blockIdx.x * blockDim.x + threadIdx.x) >> 5;
    const int nwarps = (gridDim.x * blockDim.x) >> 5;
    const int c0 = lane, c1 = lane + 32;

    float s0 = 0.f, s1 = 0.f, q0 = 0.f, q1 = 0.f;

    for (int node = warp; node < Nn; node += nwarps) {
        int r0 = g_rowptr[node], r1 = g_rowptr[node + 1];
        float a0 = hws[(size_t)node * 64 + c0];
        float a1 = hws[(size_t)node * 64 + c1];
        int p = r0;
        for (; p + 4 <= r1; p += 4) {
            int sA = g_cols[p], sB = g_cols[p + 1], sC = g_cols[p + 2], sD = g_cols[p + 3];
            float vA0 = hws[(size_t)sA * 64 + c0];
            float vB0 = hws[(size_t)sB * 64 + c0];
            float vC0 = hws[(size_t)sC * 64 + c0];
            float vD0 = hws[(size_t)sD * 64 + c0];
            float vA1 = hws[(size_t)sA * 64 + c1];
            float vB1 = hws[(size_t)sB * 64 + c1];
            float vC1 = hws[(size_t)sC * 64 + c1];
            float vD1 = hws[(size_t)sD * 64 + c1];
            a0 += (vA0 + vB0) + (vC0 + vD0);
            a1 += (vA1 + vB1) + (vC1 + vD1);
        }
        for (; p < r1; p++) {
            int s = g_cols[p];
            a0 += hws[(size_t)s * 64 + c0];
            a1 += hws[(size_t)s * 64 + c1];
        }
        float dn = g_dis[node];
        float v0 = dn * a0 + b[c0];
        float v1 = dn * a1 + b[c1];
        pre[(size_t)node * 64 + c0] = v0;
        pre[(size_t)node * 64 + c1] = v1;
        s0 += v0; s1 += v1;
        q0 += v0 * v0; q1 += v1 * v1;
    }
    atomicAdd(&stats[c0], s0);
    atomicAdd(&stats[c1], s1);
    atomicAdd(&stats[64 + c0], q0);
    atomicAdd(&stats[64 + c1], q1);
}

// ---------------- gather H=32/16: float2 lanes, GPW edges per instruction -------
// LPN = H/2 lanes own one edge's channels; GPW = 32/LPN edge-groups per warp.
// Body consumes 2*GPW edges per iteration (matched to avg degree ~16);
// per-group strided tail is at most 1 extra step.
template <int H>
__global__ void __launch_bounds__(256) k_gather(const float* __restrict__ hws,
                                                const float* __restrict__ b,
                                                float* __restrict__ pre,
                                                float* __restrict__ stats) {
    constexpr int LPN = H / 2;        // lanes per edge (16 for H=32, 8 for H=16)
    constexpr int GPW = 32 / LPN;     // edges per warp-instruction (2 / 4)
    const int lane = threadIdx.x & 31;
    const int grp = lane / LPN;
    const int cp = lane % LPN;
    const int c0 = 2 * cp;
    const int warp = (blockIdx.x * blockDim.x + threadIdx.x) >> 5;
    const int nwarps = (gridDim.x * blockDim.x) >> 5;

    const float2 bia = *reinterpret_cast<const float2*>(b + c0);
    float sx = 0.f, sy = 0.f, qx = 0.f, qy = 0.f;

    for (int node = warp; node < Nn; node += nwarps) {
        const int r0 = g_rowptr[node], r1 = g_rowptr[node + 1];
        float ax0 = 0.f, ay0 = 0.f, ax1 = 0.f, ay1 = 0.f;
        int p = r0 + grp;
        // 2-step body: 2*GPW edges per iteration, 2 independent loads in flight/lane
        for (; p + GPW < r1; p += 2 * GPW) {
            int s0 = g_cols[p];
            int s1 = g_cols[p + GPW];
            float2 v0 = *reinterpret_cast<const float2*>(hws + (size_t)s0 * H + c0);
            float2 v1 = *reinterpret_cast<const float2*>(hws + (size_t)s1 * H + c0);
            ax0 += v0.x; ay0 += v0.y;
            ax1 += v1.x; ay1 += v1.y;
        }
        if (p < r1) {
            int s = g_cols[p];
            float2 v = *reinterpret_cast<const float2*>(hws + (size_t)s * H + c0);
            ax0 += v.x; ay0 += v.y;
        }
        float ax = ax0 + ax1, ay = ay0 + ay1;
#pragma unroll
        for (int off = LPN; off < 32; off <<= 1) {
            ax += __shfl_xor_sync(0xffffffffu, ax, off);
            ay += __shfl_xor_sync(0xffffffffu, ay, off);
        }
        if (grp == 0) {
            float2 self = *reinterpret_cast<const float2*>(hws + (size_t)node * H + c0);
            float dn = g_dis[node];
            float vx = dn * (ax + self.x) + bia.x;
            float vy = dn * (ay + self.y) + bia.y;
            *reinterpret_cast<float2*>(pre + (size_t)node * H + c0) = make_float2(vx, vy);
            sx += vx; sy += vy;
            qx += vx * vx; qy += vy * vy;
        }
    }
    if (grp == 0) {
        atomicAdd(&stats[c0], sx);
        atomicAdd(&stats[c0 + 1], sy);
        atomicAdd(&stats[H + c0], qx);
        atomicAdd(&stats[H + c0 + 1], qy);
    }
}

// ---------------- pool + head fused (last pool block runs the head) -------------
__device__ __forceinline__ int lower_bound_batch(const int* __restrict__ batch, int g) {
    int lo = 0, hi = Nn;
    while (lo < hi) {
        int m = (lo + hi) >> 1;
        if (batch[m] < g) lo = m + 1; else hi = m;
    }
    return lo;
}

__global__ void k_poolhead(const float* __restrict__ x3, const int* __restrict__ batch,
                           const float* __restrict__ stats,
                           const float* __restrict__ gamma, const float* __restrict__ beta,
                           const float* __restrict__ attn_w, const float* __restrict__ attn_b,
                           const float* __restrict__ fc1_w, const float* __restrict__ fc1_b,
                           const float* __restrict__ fc2_w, const float* __restrict__ fc2_b,
                           const float* __restrict__ out_w, const float* __restrict__ out_b,
                           float* __restrict__ out) {
    __shared__ int ss, se, slast;
    __shared__ float ssum[256], smax[256];
    int g = blockIdx.x, t = threadIdx.x;
    if (t == 0) { ss = lower_bound_batch(batch, g); se = lower_bound_batch(batch, g + 1); }
    __syncthreads();
    int s = ss, e = se;
    int c = t & 15;
    float m = stats[c] * (1.0f / Nn);
    float var = stats[16 + c] * (1.0f / Nn) - m * m;
    float rstd = rsqrtf(var + 1e-5f);
    float sc = rstd * gamma[c];
    float sh = beta[c] - m * sc;

    float sum = 0.f, mx = -3.402823466e+38f;
    for (int r = s + (t >> 4); r < e; r += 16) {
        float v = x3[(size_t)r * 16 + c] * sc + sh;
        v = v > 0.f ? v : 0.1f * v;
        sum += v;
        mx = fmaxf(mx, v);
    }
    ssum[t] = sum; smax[t] = mx;
    __syncthreads();
    for (int off = 128; off >= 16; off >>= 1) {
        if (t < off) { ssum[t] += ssum[t + off]; smax[t] = fmaxf(smax[t], smax[t + off]); }
        __syncthreads();
    }
    if (t < 16) { g_pool[g * 33 + t] = ssum[t]; g_pool[g * 33 + 16 + t] = smax[t]; }
    if (t == 0) g_pool[g * 33 + 32] = (float)(e - s);

    __threadfence();
    __syncthreads();
    if (t == 0) slast = atomicAdd(&g_pooldone, 1);
    __syncthreads();
    if (slast != Gg - 1) return;
    __threadfence();

    if (t < Gg) {
        int gg = t;
        float sm2[16], mx2[16], mean[16];
        float cnt = __ldcg(&g_pool[gg * 33 + 32]);
        float inv = 1.0f / fmaxf(cnt, 1.0f);
#pragma unroll
        for (int k = 0; k < 16; k++) {
            sm2[k] = __ldcg(&g_pool[gg * 33 + k]);
            mx2[k] = __ldcg(&g_pool[gg * 33 + 16 + k]);
            mean[k] = sm2[k] * inv;
        }
        float z[3];
#pragma unroll
        for (int j = 0; j < 3; j++) z[j] = attn_b[j];
#pragma unroll
        for (int k = 0; k < 16; k++) {
#pragma unroll
            for (int j = 0; j < 3; j++) {
                z[j] += mean[k] * attn_w[k * 3 + j]
                      + mx2[k]  * attn_w[(16 + k) * 3 + j]
                      + sm2[k]  * attn_w[(32 + k) * 3 + j];
            }
        }
        float zm = fmaxf(z[0], fmaxf(z[1], z[2]));
        float e0 = expf(z[0] - zm), e1 = expf(z[1] - zm), e2 = expf(z[2] - zm);
        float is = 1.f / (e0 + e1 + e2);
        float a0 = e0 * is, a1 = e1 * is, a2 = e2 * is;
        float xg[16];
#pragma unroll
        for (int k = 0; k < 16; k++) xg[k] = a0 * mean[k] + a1 * mx2[k] + a2 * sm2[k];
        float y1[16];
#pragma unroll
        for (int j = 0; j < 16; j++) {
            float acc = fc1_b[j];
#pragma unroll
            for (int k = 0; k < 16; k++) acc += xg[k] * fc1_w[k * 16 + j];
            y1[j] = acc > 0.f ? acc : 0.1f * acc;
        }
        float y2[8];
#pragma unroll
        for (int j = 0; j < 8; j++) {
            float acc = fc2_b[j];
#pragma unroll
            for (int k = 0; k < 16; k++) acc += y1[k] * fc2_w[k * 8 + j];
            y2[j] = acc > 0.f ? acc : 0.1f * acc;
        }
        float o = out_b[0];
#pragma unroll
        for (int k = 0; k < 8; k++) o += y2[k] * out_w[k];
        out[gg] = 1.f / (1.f + expf(-o));
    }
}

// ---------------- host launch ----------------
extern "C" void kernel_launch(void* const* d_in, const int* in_sizes, int n_in,
                              void* d_out, int out_size) {
    const float* x      = (const float*)d_in[0];
    const float* W1     = (const float*)d_in[1];
    const float* b1     = (const float*)d_in[2];
    const float* W2     = (const float*)d_in[3];
    const float* b2     = (const float*)d_in[4];
    const float* W3     = (const float*)d_in[5];
    const float* b3     = (const float*)d_in[6];
    const float* g1     = (const float*)d_in[7];
    const float* be1    = (const float*)d_in[8];
    const float* g2     = (const float*)d_in[9];
    const float* be2    = (const float*)d_in[10];
    const float* g3     = (const float*)d_in[11];
    const float* be3    = (const float*)d_in[12];
    const float* attn_w = (const float*)d_in[13];
    const float* attn_b = (const float*)d_in[14];
    const float* fc1_w  = (const float*)d_in[15];
    const float* fc1_b  = (const float*)d_in[16];
    const float* fc2_w  = (const float*)d_in[17];
    const float* fc2_b  = (const float*)d_in[18];
    const float* out_w  = (const float*)d_in[19];
    const float* out_b  = (const float*)d_in[20];
    const int*   ei     = (const int*)d_in[21];
    const int*   batch  = (const int*)d_in[22];

    const int* src = ei;
    const int* dst = ei + Ee;
    float* out = (float*)d_out;

    void *pA = nullptr, *pB = nullptr, *pS = nullptr;
    cudaGetSymbolAddress(&pA, g_bufA);
    cudaGetSymbolAddress(&pB, g_bufB);
    cudaGetSymbolAddress(&pS, g_stats);
    float* bufA = (float*)pA;
    float* bufB = (float*)pB;
    float* st0 = (float*)pS;
    float* st1 = st0 + 128;
    float* st2 = st0 + 256;

    static cudaStream_t sB = nullptr;
    static cudaEvent_t evFork = nullptr, evJoin = nullptr;
    if (sB == nullptr) {
        cudaStreamCreateWithFlags(&sB, cudaStreamNonBlocking);
        cudaEventCreateWithFlags(&evFork, cudaEventDisableTiming);
        cudaEventCreateWithFlags(&evJoin, cudaEventDisableTiming);
    }

    const int gemm_grid = (Nn + 127) / 128;   // 782
    const int gather_grid = 1184;             // 148 SMs * 8 blocks

    // ---- prefix: degree + dis (round-5 skeleton) ----
    k_zero<<<(Nn + 255) / 256, 256>>>();
    k_hist<<<(Ee + 255) / 256, 256>>>(dst);
    k_dis<<<(Nn + 255) / 256, 256>>>();
    cudaEventRecord(evFork, 0);

    // ---- branch B: GEMM1 (needs only dis), overlaps scan/fill ----
    cudaStreamWaitEvent(sB, evFork, 0);
    k_gemm<128, 64, false><<<gemm_grid, 128, 0, sB>>>(x, W1, nullptr, nullptr, nullptr, bufA);
    cudaEventRecord(evJoin, sB);

    // ---- branch A (main stream): CSR scan + fill ----
    k_scan1<<<SCAN_NB, 512>>>();
    k_scan2<<<1, 256>>>();
    k_scan3<<<SCAN_NB, 512>>>();
    k_fill<<<(Ee + 255) / 256, 256>>>(src, dst);

    // ---- join: gather needs CSR + GEMM1 output ----
    cudaStreamWaitEvent(0, evJoin, 0);
    k_gather64<<<gather_grid, 256>>>(bufA, b1, bufB, st0);

    // Layer 2: 64 -> 32 (BN1 + lrelu fused into GEMM load)
    k_gemm<64, 32, true><<<gemm_grid, 128>>>(bufB, W2, st0, g1, be1, bufA);
    k_gather<32><<<gather_grid, 256>>>(bufA, b2, bufB, st1);

    // Layer 3: 32 -> 16 (BN2 + lrelu fused into GEMM load)
    k_gemm<32, 16, true><<<gemm_grid, 128>>>(bufB, W3, st1, g2, be2, bufA);
    k_gather<16><<<gather_grid, 256>>>(bufA, b3, bufB, st2);

    // Pool (BN3 + lrelu fused) + head (fused)
    k_poolhead<<<Gg, 256>>>(bufB, batch, st2, g3, be3,
                            attn_w, attn_b, fc1_w, fc1_b, fc2_w, fc2_b,
                            out_w, out_b, out);
}

// round 13
// speedup vs baseline: 1.3864x; 1.2006x over previous
#include <cuda_runtime.h>
#include <cuda_bf16.h>
#include <math.h>

#define Nn 100000
#define Ee 1600000
#define Gg 64

// ---------------- packed f32x2 helpers ----------------
#define PACK2(out, a, b) \
    asm("mov.b64 %0, {%1, %2};" : "=l"(out) : "f"(a), "f"(b))
#define FMA2(acc, a, b) \
    asm("fma.rn.f32x2 %0, %1, %2, %0;" : "+l"(acc) : "l"(a), "l"(b))

// ---------------- device scratch (static, no runtime allocation) ----------------
__device__ int   g_cnt[Nn];
__device__ int   g_rowptr[Nn + 1];
__device__ int   g_cursor[Nn];
__device__ int   g_cols[Ee];
__device__ float g_dis[Nn];
__device__ float g_bufA[Nn * 64];
__device__ float g_bufB[Nn * 64];
__device__ float g_stats[3 * 128];      // per layer: [0..H) sum, [H..2H) sumsq
__device__ int   g_bsum[256];           // scan partials
__device__ float g_pool[Gg * 33];       // per graph: sum[16], max[16], count
__device__ int   g_pooldone;            // pool completion counter

// ---------------- small utility kernels (round-5 skeleton) ----------------------
__global__ void k_zero() {
    int i = blockIdx.x * 256 + threadIdx.x;
    if (i < Nn) g_cnt[i] = 0;
    if (i < 3 * 128) g_stats[i] = 0.f;
    if (i == 0) g_pooldone = 0;
}
__global__ void k_hist(const int4* __restrict__ dst4) {
    int e = blockIdx.x * 256 + threadIdx.x;
    if (e < Ee / 4) {
        int4 d = dst4[e];
        atomicAdd(&g_cnt[d.x], 1);
        atomicAdd(&g_cnt[d.y], 1);
        atomicAdd(&g_cnt[d.z], 1);
        atomicAdd(&g_cnt[d.w], 1);
    }
}
__global__ void k_dis() {
    int i = blockIdx.x * 256 + threadIdx.x;
    if (i < Nn) g_dis[i] = rsqrtf((float)(g_cnt[i] + 1));
}

#define SCAN_NB 196   // 196 * 512 = 100352 >= Nn

__global__ void k_scan1() {
    __shared__ int sh[512];
    int t = threadIdx.x, idx = blockIdx.x * 512 + t;
    sh[t] = (idx < Nn) ? g_cnt[idx] : 0;
    __syncthreads();
    for (int off = 256; off > 0; off >>= 1) {
        if (t < off) sh[t] += sh[t + off];
        __syncthreads();
    }
    if (t == 0) g_bsum[blockIdx.x] = sh[0];
}
__global__ void k_scan2() {
    __shared__ int sh[256];
    int t = threadIdx.x;
    int v = (t < SCAN_NB) ? g_bsum[t] : 0;
    sh[t] = v;
    __syncthreads();
    for (int off = 1; off < 256; off <<= 1) {
        int add = (t >= off) ? sh[t - off] : 0;
        __syncthreads();
        sh[t] += add;
        __syncthreads();
    }
    if (t < SCAN_NB) g_bsum[t] = sh[t] - v;   // exclusive
    if (t == 0) g_rowptr[Nn] = Ee;
}
__global__ void k_scan3() {
    __shared__ int sh[512];
    int t = threadIdx.x, idx = blockIdx.x * 512 + t;
    int v = (idx < Nn) ? g_cnt[idx] : 0;
    sh[t] = v;
    __syncthreads();
    for (int off = 1; off < 512; off <<= 1) {
        int add = (t >= off) ? sh[t - off] : 0;
        __syncthreads();
        sh[t] += add;
        __syncthreads();
    }
    if (idx < Nn) {
        int ex = g_bsum[blockIdx.x] + sh[t] - v;
        g_rowptr[idx] = ex;
        g_cursor[idx] = ex;
    }
}
__global__ void k_fill(const int4* __restrict__ src4, const int4* __restrict__ dst4) {
    int e = blockIdx.x * 256 + threadIdx.x;
    if (e < Ee / 4) {
        int4 s = src4[e];
        int4 d = dst4[e];
        g_cols[atomicAdd(&g_cursor[d.x], 1)] = s.x;
        g_cols[atomicAdd(&g_cursor[d.y], 1)] = s.y;
        g_cols[atomicAdd(&g_cursor[d.z], 1)] = s.z;
        g_cols[atomicAdd(&g_cursor[d.w], 1)] = s.w;
    }
}

// ---------------- GEMM (exact round-5 body: fp32, transposed-x, packed f32x2) ---
template <int K, int H, bool NORM>
__global__ void __launch_bounds__(128, 4) k_gemm(const float* __restrict__ h,
                                                 const float* __restrict__ W,
                                                 const float* __restrict__ stats,
                                                 const float* __restrict__ gamma,
                                                 const float* __restrict__ beta,
                                                 float* __restrict__ out) {
    constexpr int C = H / 4;
    __shared__ float Wsm[16 * H];
    __shared__ float xt[16][128];
    __shared__ float nsc[K], nsh[K];
    const int tid = threadIdx.x;
    const int base = blockIdx.x * 128;
    const int n0 = (tid & 31) * 4;
    const int cg = tid >> 5;
    const int cbase = cg * C;

    if (NORM) {
        for (int c = tid; c < K; c += 128) {
            float m = stats[c] * (1.0f / Nn);
            float var = stats[K + c] * (1.0f / Nn) - m * m;
            float rstd = rsqrtf(var + 1e-5f);
            float sc = rstd * gamma[c];
            nsc[c] = sc;
            nsh[c] = beta[c] - m * sc;
        }
        __syncthreads();
    }

    unsigned long long acc2[4][C / 2];
#pragma unroll
    for (int t = 0; t < 4; t++)
#pragma unroll
        for (int j = 0; j < C / 2; j++) acc2[t][j] = 0ull;

    const int myrow = base + tid;

    for (int kc = 0; kc < K; kc += 16) {
        {
            const float4* Wg = reinterpret_cast<const float4*>(W + kc * H);
            float4* Ws = reinterpret_cast<float4*>(Wsm);
#pragma unroll
            for (int i = tid; i < 16 * H / 4; i += 128) Ws[i] = Wg[i];
        }
#pragma unroll
        for (int q = 0; q < 4; q++) {
            float4 v = make_float4(0.f, 0.f, 0.f, 0.f);
            if (myrow < Nn)
                v = *reinterpret_cast<const float4*>(h + (size_t)myrow * K + kc + q * 4);
            if (NORM) {
                int cb = kc + q * 4;
                v.x = v.x * nsc[cb + 0] + nsh[cb + 0]; v.x = v.x > 0.f ? v.x : 0.1f * v.x;
                v.y = v.y * nsc[cb + 1] + nsh[cb + 1]; v.y = v.y > 0.f ? v.y : 0.1f * v.y;
                v.z = v.z * nsc[cb + 2] + nsh[cb + 2]; v.z = v.z > 0.f ? v.z : 0.1f * v.z;
                v.w = v.w * nsc[cb + 3] + nsh[cb + 3]; v.w = v.w > 0.f ? v.w : 0.1f * v.w;
            }
            xt[q * 4 + 0][tid] = v.x;
            xt[q * 4 + 1][tid] = v.y;
            xt[q * 4 + 2][tid] = v.z;
            xt[q * 4 + 3][tid] = v.w;
        }
        __syncthreads();
#pragma unroll
        for (int kk = 0; kk < 16; kk++) {
            float4 xv = *reinterpret_cast<const float4*>(&xt[kk][n0]);
            unsigned long long x0, x1, x2, x3;
            PACK2(x0, xv.x, xv.x);
            PACK2(x1, xv.y, xv.y);
            PACK2(x2, xv.z, xv.z);
            PACK2(x3, xv.w, xv.w);
            const ulonglong2* w2 =
                reinterpret_cast<const ulonglong2*>(&Wsm[kk * H + cbase]);
#pragma unroll
            for (int j = 0; j < C / 4; j++) {
                ulonglong2 w = w2[j];
                FMA2(acc2[0][2 * j + 0], x0, w.x);
                FMA2(acc2[0][2 * j + 1], x0, w.y);
                FMA2(acc2[1][2 * j + 0], x1, w.x);
                FMA2(acc2[1][2 * j + 1], x1, w.y);
                FMA2(acc2[2][2 * j + 0], x2, w.x);
                FMA2(acc2[2][2 * j + 1], x2, w.y);
                FMA2(acc2[3][2 * j + 0], x3, w.x);
                FMA2(acc2[3][2 * j + 1], x3, w.y);
            }
        }
        __syncthreads();
    }

#pragma unroll
    for (int t = 0; t < 4; t++) {
        int node = base + n0 + t;
        if (node < Nn) {
            float dn = g_dis[node];
            const float* a = reinterpret_cast<const float*>(acc2[t]);
            float* o = out + (size_t)node * H + cbase;
#pragma unroll
            for (int j = 0; j < C / 4; j++) {
                float4 r;
                r.x = a[4 * j + 0] * dn;
                r.y = a[4 * j + 1] * dn;
                r.z = a[4 * j + 2] * dn;
                r.w = a[4 * j + 3] * dn;
                *reinterpret_cast<float4*>(o + 4 * j) = r;
            }
        }
    }
}

// ---------------- gather (EXACT round-5 body): one warp per node, scalar NCH ----
template <int H>
__global__ void __launch_bounds__(256) k_gather(const float* __restrict__ hws,
                                                const float* __restrict__ b,
                                                float* __restrict__ pre,
                                                float* __restrict__ stats) {
    constexpr int NCH = (H >= 32) ? H / 32 : 1;
    const int lane = threadIdx.x & 31;
    const int warp = (blockIdx.x * blockDim.x + threadIdx.x) >> 5;
    const int nwarps = (gridDim.x * blockDim.x) >> 5;
    const bool act = (H >= 32) || (lane < H);

    int c[NCH];
#pragma unroll
    for (int j = 0; j < NCH; j++) c[j] = lane + 32 * j;

    float s_sum[NCH], s_sq[NCH];
#pragma unroll
    for (int j = 0; j < NCH; j++) { s_sum[j] = 0.f; s_sq[j] = 0.f; }

    for (int node = warp; node < Nn; node += nwarps) {
        int r0 = g_rowptr[node], r1 = g_rowptr[node + 1];
        float acc[NCH];
        if (act) {
#pragma unroll
            for (int j = 0; j < NCH; j++) acc[j] = hws[(size_t)node * H + c[j]];
        } else {
#pragma unroll
            for (int j = 0; j < NCH; j++) acc[j] = 0.f;
        }
        int p = r0;
        for (; p + 4 <= r1; p += 4) {
            int s0 = g_cols[p], s1 = g_cols[p + 1], s2 = g_cols[p + 2], s3 = g_cols[p + 3];
            if (act) {
#pragma unroll
                for (int j = 0; j < NCH; j++) {
                    float v0 = hws[(size_t)s0 * H + c[j]];
                    float v1 = hws[(size_t)s1 * H + c[j]];
                    float v2 = hws[(size_t)s2 * H + c[j]];
                    float v3 = hws[(size_t)s3 * H + c[j]];
                    acc[j] += (v0 + v1) + (v2 + v3);
                }
            }
        }
        for (; p < r1; p++) {
            int s = g_cols[p];
            if (act) {
#pragma unroll
                for (int j = 0; j < NCH; j++) acc[j] += hws[(size_t)s * H + c[j]];
            }
        }
        if (act) {
            float dn = g_dis[node];
#pragma unroll
            for (int j = 0; j < NCH; j++) {
                float v = dn * acc[j] + b[c[j]];
                pre[(size_t)node * H + c[j]] = v;
                s_sum[j] += v;
                s_sq[j] += v * v;
            }
        }
    }
    if (act) {
#pragma unroll
        for (int j = 0; j < NCH; j++) {
            atomicAdd(&stats[c[j]], s_sum[j]);
            atomicAdd(&stats[H + c[j]], s_sq[j]);
        }
    }
}

// ---------------- pool + head fused (last pool block runs the head) -------------
__device__ __forceinline__ int lower_bound_batch(const int* __restrict__ batch, int g) {
    int lo = 0, hi = Nn;
    while (lo < hi) {
        int m = (lo + hi) >> 1;
        if (batch[m] < g) lo = m + 1; else hi = m;
    }
    return lo;
}

__global__ void k_poolhead(const float* __restrict__ x3, const int* __restrict__ batch,
                           const float* __restrict__ stats,
                           const float* __restrict__ gamma, const float* __restrict__ beta,
                           const float* __restrict__ attn_w, const float* __restrict__ attn_b,
                           const float* __restrict__ fc1_w, const float* __restrict__ fc1_b,
                           const float* __restrict__ fc2_w, const float* __restrict__ fc2_b,
                           const float* __restrict__ out_w, const float* __restrict__ out_b,
                           float* __restrict__ out) {
    __shared__ int ss, se, slast;
    __shared__ float ssum[256], smax[256];
    int g = blockIdx.x, t = threadIdx.x;
    if (t == 0) { ss = lower_bound_batch(batch, g); se = lower_bound_batch(batch, g + 1); }
    __syncthreads();
    int s = ss, e = se;
    int c = t & 15;
    float m = stats[c] * (1.0f / Nn);
    float var = stats[16 + c] * (1.0f / Nn) - m * m;
    float rstd = rsqrtf(var + 1e-5f);
    float sc = rstd * gamma[c];
    float sh = beta[c] - m * sc;

    float sum = 0.f, mx = -3.402823466e+38f;
    for (int r = s + (t >> 4); r < e; r += 16) {
        float v = x3[(size_t)r * 16 + c] * sc + sh;
        v = v > 0.f ? v : 0.1f * v;
        sum += v;
        mx = fmaxf(mx, v);
    }
    ssum[t] = sum; smax[t] = mx;
    __syncthreads();
    for (int off = 128; off >= 16; off >>= 1) {
        if (t < off) { ssum[t] += ssum[t + off]; smax[t] = fmaxf(smax[t], smax[t + off]); }
        __syncthreads();
    }
    if (t < 16) { g_pool[g * 33 + t] = ssum[t]; g_pool[g * 33 + 16 + t] = smax[t]; }
    if (t == 0) g_pool[g * 33 + 32] = (float)(e - s);

    __threadfence();
    __syncthreads();
    if (t == 0) slast = atomicAdd(&g_pooldone, 1);
    __syncthreads();
    if (slast != Gg - 1) return;
    __threadfence();

    if (t < Gg) {
        int gg = t;
        float sm2[16], mx2[16], mean[16];
        float cnt = __ldcg(&g_pool[gg * 33 + 32]);
        float inv = 1.0f / fmaxf(cnt, 1.0f);
#pragma unroll
        for (int k = 0; k < 16; k++) {
            sm2[k] = __ldcg(&g_pool[gg * 33 + k]);
            mx2[k] = __ldcg(&g_pool[gg * 33 + 16 + k]);
            mean[k] = sm2[k] * inv;
        }
        float z[3];
#pragma unroll
        for (int j = 0; j < 3; j++) z[j] = attn_b[j];
#pragma unroll
        for (int k = 0; k < 16; k++) {
#pragma unroll
            for (int j = 0; j < 3; j++) {
                z[j] += mean[k] * attn_w[k * 3 + j]
                      + mx2[k]  * attn_w[(16 + k) * 3 + j]
                      + sm2[k]  * attn_w[(32 + k) * 3 + j];
            }
        }
        float zm = fmaxf(z[0], fmaxf(z[1], z[2]));
        float e0 = expf(z[0] - zm), e1 = expf(z[1] - zm), e2 = expf(z[2] - zm);
        float is = 1.f / (e0 + e1 + e2);
        float a0 = e0 * is, a1 = e1 * is, a2 = e2 * is;
        float xg[16];
#pragma unroll
        for (int k = 0; k < 16; k++) xg[k] = a0 * mean[k] + a1 * mx2[k] + a2 * sm2[k];
        float y1[16];
#pragma unroll
        for (int j = 0; j < 16; j++) {
            float acc = fc1_b[j];
#pragma unroll
            for (int k = 0; k < 16; k++) acc += xg[k] * fc1_w[k * 16 + j];
            y1[j] = acc > 0.f ? acc : 0.1f * acc;
        }
        float y2[8];
#pragma unroll
        for (int j = 0; j < 8; j++) {
            float acc = fc2_b[j];
#pragma unroll
            for (int k = 0; k < 16; k++) acc += y1[k] * fc2_w[k * 8 + j];
            y2[j] = acc > 0.f ? acc : 0.1f * acc;
        }
        float o = out_b[0];
#pragma unroll
        for (int k = 0; k < 8; k++) o += y2[k] * out_w[k];
        out[gg] = 1.f / (1.f + expf(-o));
    }
}

// ---------------- host launch (round-5 structure) --------------------------------
extern "C" void kernel_launch(void* const* d_in, const int* in_sizes, int n_in,
                              void* d_out, int out_size) {
    const float* x      = (const float*)d_in[0];
    const float* W1     = (const float*)d_in[1];
    const float* b1     = (const float*)d_in[2];
    const float* W2     = (const float*)d_in[3];
    const float* b2     = (const float*)d_in[4];
    const float* W3     = (const float*)d_in[5];
    const float* b3     = (const float*)d_in[6];
    const float* g1     = (const float*)d_in[7];
    const float* be1    = (const float*)d_in[8];
    const float* g2     = (const float*)d_in[9];
    const float* be2    = (const float*)d_in[10];
    const float* g3     = (const float*)d_in[11];
    const float* be3    = (const float*)d_in[12];
    const float* attn_w = (const float*)d_in[13];
    const float* attn_b = (const float*)d_in[14];
    const float* fc1_w  = (const float*)d_in[15];
    const float* fc1_b  = (const float*)d_in[16];
    const float* fc2_w  = (const float*)d_in[17];
    const float* fc2_b  = (const float*)d_in[18];
    const float* out_w  = (const float*)d_in[19];
    const float* out_b  = (const float*)d_in[20];
    const int*   ei     = (const int*)d_in[21];
    const int*   batch  = (const int*)d_in[22];

    const int* src = ei;
    const int* dst = ei + Ee;
    float* out = (float*)d_out;

    void *pA = nullptr, *pB = nullptr, *pS = nullptr;
    cudaGetSymbolAddress(&pA, g_bufA);
    cudaGetSymbolAddress(&pB, g_bufB);
    cudaGetSymbolAddress(&pS, g_stats);
    float* bufA = (float*)pA;
    float* bufB = (float*)pB;
    float* st0 = (float*)pS;
    float* st1 = st0 + 128;
    float* st2 = st0 + 256;

    static cudaStream_t sB = nullptr;
    static cudaEvent_t evFork = nullptr, evJoin = nullptr;
    if (sB == nullptr) {
        cudaStreamCreateWithFlags(&sB, cudaStreamNonBlocking);
        cudaEventCreateWithFlags(&evFork, cudaEventDisableTiming);
        cudaEventCreateWithFlags(&evJoin, cudaEventDisableTiming);
    }

    const int gemm_grid = (Nn + 127) / 128;   // 782
    const int gather_grid = 1184;             // 148 SMs * 8 blocks

    // ---- prefix: degree + dis ----
    k_zero<<<(Nn + 255) / 256, 256>>>();
    k_hist<<<(Ee / 4 + 255) / 256, 256>>>((const int4*)dst);
    k_dis<<<(Nn + 255) / 256, 256>>>();
    cudaEventRecord(evFork, 0);

    // ---- branch B: GEMM1 (needs only dis), overlaps scan/fill ----
    cudaStreamWaitEvent(sB, evFork, 0);
    k_gemm<128, 64, false><<<gemm_grid, 128, 0, sB>>>(x, W1, nullptr, nullptr, nullptr, bufA);
    cudaEventRecord(evJoin, sB);

    // ---- branch A (main stream): CSR scan + fill ----
    k_scan1<<<SCAN_NB, 512>>>();
    k_scan2<<<1, 256>>>();
    k_scan3<<<SCAN_NB, 512>>>();
    k_fill<<<(Ee / 4 + 255) / 256, 256>>>((const int4*)src, (const int4*)dst);

    // ---- join: gather needs CSR + GEMM1 output ----
    cudaStreamWaitEvent(0, evJoin, 0);
    k_gather<64><<<gather_grid, 256>>>(bufA, b1, bufB, st0);

    // Layer 2: 64 -> 32 (BN1 + lrelu fused into GEMM load)
    k_gemm<64, 32, true><<<gemm_grid, 128>>>(bufB, W2, st0, g1, be1, bufA);
    k_gather<32><<<gather_grid, 256>>>(bufA, b2, bufB, st1);

    // Layer 3: 32 -> 16 (BN2 + lrelu fused into GEMM load)
    k_gemm<32, 16, true><<<gemm_grid, 128>>>(bufB, W3, st1, g2, be2, bufA);
    k_gather<16><<<gather_grid, 256>>>(bufA, b3, bufB, st2);

    // Pool (BN3 + lrelu fused) + head (fused)
    k_poolhead<<<Gg, 256>>>(bufB, batch, st2, g3, be3,
                            attn_w, attn_b, fc1_w, fc1_b, fc2_w, fc2_b,
                            out_w, out_b, out);
}

// round 14
// speedup vs baseline: 1.4046x; 1.0132x over previous
#include <cuda_runtime.h>
#include <cuda_bf16.h>
#include <math.h>

#define Nn 100000
#define Ee 1600000
#define Gg 64

// ---------------- packed f32x2 helpers ----------------
#define PACK2(out, a, b) \
    asm("mov.b64 %0, {%1, %2};" : "=l"(out) : "f"(a), "f"(b))
#define FMA2(acc, a, b) \
    asm("fma.rn.f32x2 %0, %1, %2, %0;" : "+l"(acc) : "l"(a), "l"(b))

// ---------------- device scratch (static, no runtime allocation) ----------------
__device__ int   g_cnt[Nn];
__device__ int   g_rowptr[Nn + 1];
__device__ int   g_cursor[Nn];
__device__ int   g_cols[Ee];
__device__ float g_dis[Nn];
__device__ float g_bufA[Nn * 64];
__device__ float g_bufB[Nn * 64];
__device__ float g_stats[3 * 128];      // per layer: [0..H) sum, [H..2H) sumsq
__device__ int   g_bsum[256];           // scan partials
__device__ float g_pool[Gg * 33];       // per graph: sum[16], max[16], count

// ---------------- small utility kernels (exact round-5) -------------------------
__global__ void k_zero() {
    int i = blockIdx.x * 256 + threadIdx.x;
    if (i < Nn) g_cnt[i] = 0;
    if (i < 3 * 128) g_stats[i] = 0.f;
}
__global__ void k_hist(const int* __restrict__ dst) {
    int e = blockIdx.x * 256 + threadIdx.x;
    if (e < Ee) atomicAdd(&g_cnt[dst[e]], 1);
}
__global__ void k_dis() {
    int i = blockIdx.x * 256 + threadIdx.x;
    if (i < Nn) g_dis[i] = rsqrtf((float)(g_cnt[i] + 1));
}

#define SCAN_NB 196   // 196 * 512 = 100352 >= Nn

__global__ void k_scan1() {
    __shared__ int sh[512];
    int t = threadIdx.x, idx = blockIdx.x * 512 + t;
    sh[t] = (idx < Nn) ? g_cnt[idx] : 0;
    __syncthreads();
    for (int off = 256; off > 0; off >>= 1) {
        if (t < off) sh[t] += sh[t + off];
        __syncthreads();
    }
    if (t == 0) g_bsum[blockIdx.x] = sh[0];
}
__global__ void k_scan2() {
    __shared__ int sh[256];
    int t = threadIdx.x;
    int v = (t < SCAN_NB) ? g_bsum[t] : 0;
    sh[t] = v;
    __syncthreads();
    for (int off = 1; off < 256; off <<= 1) {
        int add = (t >= off) ? sh[t - off] : 0;
        __syncthreads();
        sh[t] += add;
        __syncthreads();
    }
    if (t < SCAN_NB) g_bsum[t] = sh[t] - v;   // exclusive
    if (t == 0) g_rowptr[Nn] = Ee;
}
__global__ void k_scan3() {
    __shared__ int sh[512];
    int t = threadIdx.x, idx = blockIdx.x * 512 + t;
    int v = (idx < Nn) ? g_cnt[idx] : 0;
    sh[t] = v;
    __syncthreads();
    for (int off = 1; off < 512; off <<= 1) {
        int add = (t >= off) ? sh[t - off] : 0;
        __syncthreads();
        sh[t] += add;
        __syncthreads();
    }
    if (idx < Nn) {
        int ex = g_bsum[blockIdx.x] + sh[t] - v;
        g_rowptr[idx] = ex;
        g_cursor[idx] = ex;
    }
}
__global__ void k_fill(const int* __restrict__ src, const int* __restrict__ dst) {
    int e = blockIdx.x * 256 + threadIdx.x;
    if (e < Ee) {
        int d = dst[e];
        int p = atomicAdd(&g_cursor[d], 1);
        g_cols[p] = src[e];
    }
}

// ---------------- GEMM (exact round-5 body) --------------------------------------
template <int K, int H, bool NORM>
__global__ void __launch_bounds__(128, 4) k_gemm(const float* __restrict__ h,
                                                 const float* __restrict__ W,
                                                 const float* __restrict__ stats,
                                                 const float* __restrict__ gamma,
                                                 const float* __restrict__ beta,
                                                 float* __restrict__ out) {
    constexpr int C = H / 4;
    __shared__ float Wsm[16 * H];
    __shared__ float xt[16][128];
    __shared__ float nsc[K], nsh[K];
    const int tid = threadIdx.x;
    const int base = blockIdx.x * 128;
    const int n0 = (tid & 31) * 4;
    const int cg = tid >> 5;
    const int cbase = cg * C;

    if (NORM) {
        for (int c = tid; c < K; c += 128) {
            float m = stats[c] * (1.0f / Nn);
            float var = stats[K + c] * (1.0f / Nn) - m * m;
            float rstd = rsqrtf(var + 1e-5f);
            float sc = rstd * gamma[c];
            nsc[c] = sc;
            nsh[c] = beta[c] - m * sc;
        }
        __syncthreads();
    }

    unsigned long long acc2[4][C / 2];
#pragma unroll
    for (int t = 0; t < 4; t++)
#pragma unroll
        for (int j = 0; j < C / 2; j++) acc2[t][j] = 0ull;

    const int myrow = base + tid;

    for (int kc = 0; kc < K; kc += 16) {
        {
            const float4* Wg = reinterpret_cast<const float4*>(W + kc * H);
            float4* Ws = reinterpret_cast<float4*>(Wsm);
#pragma unroll
            for (int i = tid; i < 16 * H / 4; i += 128) Ws[i] = Wg[i];
        }
#pragma unroll
        for (int q = 0; q < 4; q++) {
            float4 v = make_float4(0.f, 0.f, 0.f, 0.f);
            if (myrow < Nn)
                v = *reinterpret_cast<const float4*>(h + (size_t)myrow * K + kc + q * 4);
            if (NORM) {
                int cb = kc + q * 4;
                v.x = v.x * nsc[cb + 0] + nsh[cb + 0]; v.x = v.x > 0.f ? v.x : 0.1f * v.x;
                v.y = v.y * nsc[cb + 1] + nsh[cb + 1]; v.y = v.y > 0.f ? v.y : 0.1f * v.y;
                v.z = v.z * nsc[cb + 2] + nsh[cb + 2]; v.z = v.z > 0.f ? v.z : 0.1f * v.z;
                v.w = v.w * nsc[cb + 3] + nsh[cb + 3]; v.w = v.w > 0.f ? v.w : 0.1f * v.w;
            }
            xt[q * 4 + 0][tid] = v.x;
            xt[q * 4 + 1][tid] = v.y;
            xt[q * 4 + 2][tid] = v.z;
            xt[q * 4 + 3][tid] = v.w;
        }
        __syncthreads();
#pragma unroll
        for (int kk = 0; kk < 16; kk++) {
            float4 xv = *reinterpret_cast<const float4*>(&xt[kk][n0]);
            unsigned long long x0, x1, x2, x3;
            PACK2(x0, xv.x, xv.x);
            PACK2(x1, xv.y, xv.y);
            PACK2(x2, xv.z, xv.z);
            PACK2(x3, xv.w, xv.w);
            const ulonglong2* w2 =
                reinterpret_cast<const ulonglong2*>(&Wsm[kk * H + cbase]);
#pragma unroll
            for (int j = 0; j < C / 4; j++) {
                ulonglong2 w = w2[j];
                FMA2(acc2[0][2 * j + 0], x0, w.x);
                FMA2(acc2[0][2 * j + 1], x0, w.y);
                FMA2(acc2[1][2 * j + 0], x1, w.x);
                FMA2(acc2[1][2 * j + 1], x1, w.y);
                FMA2(acc2[2][2 * j + 0], x2, w.x);
                FMA2(acc2[2][2 * j + 1], x2, w.y);
                FMA2(acc2[3][2 * j + 0], x3, w.x);
                FMA2(acc2[3][2 * j + 1], x3, w.y);
            }
        }
        __syncthreads();
    }

#pragma unroll
    for (int t = 0; t < 4; t++) {
        int node = base + n0 + t;
        if (node < Nn) {
            float dn = g_dis[node];
            const float* a = reinterpret_cast<const float*>(acc2[t]);
            float* o = out + (size_t)node * H + cbase;
#pragma unroll
            for (int j = 0; j < C / 4; j++) {
                float4 r;
                r.x = a[4 * j + 0] * dn;
                r.y = a[4 * j + 1] * dn;
                r.z = a[4 * j + 2] * dn;
                r.w = a[4 * j + 3] * dn;
                *reinterpret_cast<float4*>(o + 4 * j) = r;
            }
        }
    }
}

// ---------------- gather H=64 DUAL-NODE: two independent chains per warp ---------
// Per-node body identical to round-5; a warp advances two nodes in lockstep in the
// main loop (2x loads in flight), then drains each node with the original loops.
__global__ void __launch_bounds__(256) k_gather64(const float* __restrict__ hws,
                                                  const float* __restrict__ b,
                                                  float* __restrict__ pre,
                                                  float* __restrict__ stats) {
    const int lane = threadIdx.x & 31;
    const int warp = (blockIdx.x * blockDim.x + threadIdx.x) >> 5;
    const int nwarps = (gridDim.x * blockDim.x) >> 5;
    const int c0 = lane, c1 = lane + 32;

    float s0 = 0.f, s1 = 0.f, q0 = 0.f, q1 = 0.f;

    for (int base = warp * 2; base < Nn; base += nwarps * 2) {
        const int nA = base;
        const int nB = base + 1;
        const bool hasB = (nB < Nn);

        int rA0 = g_rowptr[nA], rA1 = g_rowptr[nA + 1];
        int rB0 = 0, rB1 = 0;
        if (hasB) { rB0 = g_rowptr[nB]; rB1 = g_rowptr[nB + 1]; }

        float aA0 = hws[(size_t)nA * 64 + c0];
        float aA1 = hws[(size_t)nA * 64 + c1];
        float aB0 = 0.f, aB1 = 0.f;
        if (hasB) {
            aB0 = hws[(size_t)nB * 64 + c0];
            aB1 = hws[(size_t)nB * 64 + c1];
        }

        int pA = rA0, pB = rB0;
        // paired main loop: both nodes advance together -> 2 independent chains
        while (pA + 4 <= rA1 && pB + 4 <= rB1) {
            int sA0 = g_cols[pA], sA1 = g_cols[pA + 1], sA2 = g_cols[pA + 2], sA3 = g_cols[pA + 3];
            int sB0 = g_cols[pB], sB1 = g_cols[pB + 1], sB2 = g_cols[pB + 2], sB3 = g_cols[pB + 3];
            float vA00 = hws[(size_t)sA0 * 64 + c0];
            float vA10 = hws[(size_t)sA1 * 64 + c0];
            float vA20 = hws[(size_t)sA2 * 64 + c0];
            float vA30 = hws[(size_t)sA3 * 64 + c0];
            float vB00 = hws[(size_t)sB0 * 64 + c0];
            float vB10 = hws[(size_t)sB1 * 64 + c0];
            float vB20 = hws[(size_t)sB2 * 64 + c0];
            float vB30 = hws[(size_t)sB3 * 64 + c0];
            float vA01 = hws[(size_t)sA0 * 64 + c1];
            float vA11 = hws[(size_t)sA1 * 64 + c1];
            float vA21 = hws[(size_t)sA2 * 64 + c1];
            float vA31 = hws[(size_t)sA3 * 64 + c1];
            float vB01 = hws[(size_t)sB0 * 64 + c1];
            float vB11 = hws[(size_t)sB1 * 64 + c1];
            float vB21 = hws[(size_t)sB2 * 64 + c1];
            float vB31 = hws[(size_t)sB3 * 64 + c1];
            aA0 += (vA00 + vA10) + (vA20 + vA30);
            aB0 += (vB00 + vB10) + (vB20 + vB30);
            aA1 += (vA01 + vA11) + (vA21 + vA31);
            aB1 += (vB01 + vB11) + (vB21 + vB31);
            pA += 4; pB += 4;
        }
        // drain A (original round-5 loops)
        for (; pA + 4 <= rA1; pA += 4) {
            int sA0 = g_cols[pA], sA1 = g_cols[pA + 1], sA2 = g_cols[pA + 2], sA3 = g_cols[pA + 3];
            float v00 = hws[(size_t)sA0 * 64 + c0];
            float v10 = hws[(size_t)sA1 * 64 + c0];
            float v20 = hws[(size_t)sA2 * 64 + c0];
            float v30 = hws[(size_t)sA3 * 64 + c0];
            float v01 = hws[(size_t)sA0 * 64 + c1];
            float v11 = hws[(size_t)sA1 * 64 + c1];
            float v21 = hws[(size_t)sA2 * 64 + c1];
            float v31 = hws[(size_t)sA3 * 64 + c1];
            aA0 += (v00 + v10) + (v20 + v30);
            aA1 += (v01 + v11) + (v21 + v31);
        }
        for (; pA < rA1; pA++) {
            int s = g_cols[pA];
            aA0 += hws[(size_t)s * 64 + c0];
            aA1 += hws[(size_t)s * 64 + c1];
        }
        // drain B
        for (; pB + 4 <= rB1; pB += 4) {
            int sB0 = g_cols[pB], sB1 = g_cols[pB + 1], sB2 = g_cols[pB + 2], sB3 = g_cols[pB + 3];
            float v00 = hws[(size_t)sB0 * 64 + c0];
            float v10 = hws[(size_t)sB1 * 64 + c0];
            float v20 = hws[(size_t)sB2 * 64 + c0];
            float v30 = hws[(size_t)sB3 * 64 + c0];
            float v01 = hws[(size_t)sB0 * 64 + c1];
            float v11 = hws[(size_t)sB1 * 64 + c1];
            float v21 = hws[(size_t)sB2 * 64 + c1];
            float v31 = hws[(size_t)sB3 * 64 + c1];
            aB0 += (v00 + v10) + (v20 + v30);
            aB1 += (v01 + v11) + (v21 + v31);
        }
        for (; pB < rB1; pB++) {
            int s = g_cols[pB];
            aB0 += hws[(size_t)s * 64 + c0];
            aB1 += hws[(size_t)s * 64 + c1];
        }

        // epilogues
        {
            float dn = g_dis[nA];
            float v0 = dn * aA0 + b[c0];
            float v1 = dn * aA1 + b[c1];
            pre[(size_t)nA * 64 + c0] = v0;
            pre[(size_t)nA * 64 + c1] = v1;
            s0 += v0; s1 += v1;
            q0 += v0 * v0; q1 += v1 * v1;
        }
        if (hasB) {
            float dn = g_dis[nB];
            float v0 = dn * aB0 + b[c0];
            float v1 = dn * aB1 + b[c1];
            pre[(size_t)nB * 64 + c0] = v0;
            pre[(size_t)nB * 64 + c1] = v1;
            s0 += v0; s1 += v1;
            q0 += v0 * v0; q1 += v1 * v1;
        }
    }
    atomicAdd(&stats[c0], s0);
    atomicAdd(&stats[c1], s1);
    atomicAdd(&stats[64 + c0], q0);
    atomicAdd(&stats[64 + c1], q1);
}

// ---------------- gather (EXACT round-5 body) for H=32/16 ------------------------
template <int H>
__global__ void __launch_bounds__(256) k_gather(const float* __restrict__ hws,
                                                const float* __restrict__ b,
                                                float* __restrict__ pre,
                                                float* __restrict__ stats) {
    constexpr int NCH = (H >= 32) ? H / 32 : 1;
    const int lane = threadIdx.x & 31;
    const int warp = (blockIdx.x * blockDim.x + threadIdx.x) >> 5;
    const int nwarps = (gridDim.x * blockDim.x) >> 5;
    const bool act = (H >= 32) || (lane < H);

    int c[NCH];
#pragma unroll
    for (int j = 0; j < NCH; j++) c[j] = lane + 32 * j;

    float s_sum[NCH], s_sq[NCH];
#pragma unroll
    for (int j = 0; j < NCH; j++) { s_sum[j] = 0.f; s_sq[j] = 0.f; }

    for (int node = warp; node < Nn; node += nwarps) {
        int r0 = g_rowptr[node], r1 = g_rowptr[node + 1];
        float acc[NCH];
        if (act) {
#pragma unroll
            for (int j = 0; j < NCH; j++) acc[j] = hws[(size_t)node * H + c[j]];
        } else {
#pragma unroll
            for (int j = 0; j < NCH; j++) acc[j] = 0.f;
        }
        int p = r0;
        for (; p + 4 <= r1; p += 4) {
            int s0 = g_cols[p], s1 = g_cols[p + 1], s2 = g_cols[p + 2], s3 = g_cols[p + 3];
            if (act) {
#pragma unroll
                for (int j = 0; j < NCH; j++) {
                    float v0 = hws[(size_t)s0 * H + c[j]];
                    float v1 = hws[(size_t)s1 * H + c[j]];
                    float v2 = hws[(size_t)s2 * H + c[j]];
                    float v3 = hws[(size_t)s3 * H + c[j]];
                    acc[j] += (v0 + v1) + (v2 + v3);
                }
            }
        }
        for (; p < r1; p++) {
            int s = g_cols[p];
            if (act) {
#pragma unroll
                for (int j = 0; j < NCH; j++) acc[j] += hws[(size_t)s * H + c[j]];
            }
        }
        if (act) {
            float dn = g_dis[node];
#pragma unroll
            for (int j = 0; j < NCH; j++) {
                float v = dn * acc[j] + b[c[j]];
                pre[(size_t)node * H + c[j]] = v;
                s_sum[j] += v;
                s_sq[j] += v * v;
            }
        }
    }
    if (act) {
#pragma unroll
        for (int j = 0; j < NCH; j++) {
            atomicAdd(&stats[c[j]], s_sum[j]);
            atomicAdd(&stats[H + c[j]], s_sq[j]);
        }
    }
}

// ---------------- pooling (exact round-5) ----------------------------------------
__device__ __forceinline__ int lower_bound_batch(const int* __restrict__ batch, int g) {
    int lo = 0, hi = Nn;
    while (lo < hi) {
        int m = (lo + hi) >> 1;
        if (batch[m] < g) lo = m + 1; else hi = m;
    }
    return lo;
}

__global__ void k_pool(const float* __restrict__ x3, const int* __restrict__ batch,
                       const float* __restrict__ stats,
                       const float* __restrict__ gamma, const float* __restrict__ beta) {
    __shared__ int ss, se;
    __shared__ float ssum[256], smax[256];
    int g = blockIdx.x, t = threadIdx.x;
    if (t == 0) { ss = lower_bound_batch(batch, g); se = lower_bound_batch(batch, g + 1); }
    __syncthreads();
    int s = ss, e = se;
    int c = t & 15;
    float m = stats[c] * (1.0f / Nn);
    float var = stats[16 + c] * (1.0f / Nn) - m * m;
    float rstd = rsqrtf(var + 1e-5f);
    float sc = rstd * gamma[c];
    float sh = beta[c] - m * sc;

    float sum = 0.f, mx = -3.402823466e+38f;
    for (int r = s + (t >> 4); r < e; r += 16) {
        float v = x3[(size_t)r * 16 + c] * sc + sh;
        v = v > 0.f ? v : 0.1f * v;
        sum += v;
        mx = fmaxf(mx, v);
    }
    ssum[t] = sum; smax[t] = mx;
    __syncthreads();
    for (int off = 128; off >= 16; off >>= 1) {
        if (t < off) { ssum[t] += ssum[t + off]; smax[t] = fmaxf(smax[t], smax[t + off]); }
        __syncthreads();
    }
    if (t < 16) { g_pool[g * 33 + t] = ssum[t]; g_pool[g * 33 + 16 + t] = smax[t]; }
    if (t == 0) g_pool[g * 33 + 32] = (float)(e - s);
}

// ---------------- head (exact round-5) --------------------------------------------
__global__ void k_head(const float* __restrict__ attn_w, const float* __restrict__ attn_b,
                       const float* __restrict__ fc1_w, const float* __restrict__ fc1_b,
                       const float* __restrict__ fc2_w, const float* __restrict__ fc2_b,
                       const float* __restrict__ out_w, const float* __restrict__ out_b,
                       float* __restrict__ out) {
    int g = threadIdx.x;
    if (g >= Gg) return;
    float sm[16], mx[16], mean[16];
    float cnt = g_pool[g * 33 + 32];
    float inv = 1.0f / fmaxf(cnt, 1.0f);
#pragma unroll
    for (int k = 0; k < 16; k++) {
        sm[k] = g_pool[g * 33 + k];
        mx[k] = g_pool[g * 33 + 16 + k];
        mean[k] = sm[k] * inv;
    }
    float z[3];
#pragma unroll
    for (int j = 0; j < 3; j++) z[j] = attn_b[j];
#pragma unroll
    for (int k = 0; k < 16; k++) {
#pragma unroll
        for (int j = 0; j < 3; j++) {
            z[j] += mean[k] * attn_w[k * 3 + j]
                  + mx[k]   * attn_w[(16 + k) * 3 + j]
                  + sm[k]   * attn_w[(32 + k) * 3 + j];
        }
    }
    float zm = fmaxf(z[0], fmaxf(z[1], z[2]));
    float e0 = expf(z[0] - zm), e1 = expf(z[1] - zm), e2 = expf(z[2] - zm);
    float is = 1.f / (e0 + e1 + e2);
    float a0 = e0 * is, a1 = e1 * is, a2 = e2 * is;
    float xg[16];
#pragma unroll
    for (int k = 0; k < 16; k++) xg[k] = a0 * mean[k] + a1 * mx[k] + a2 * sm[k];
    float y1[16];
#pragma unroll
    for (int j = 0; j < 16; j++) {
        float acc = fc1_b[j];
#pragma unroll
        for (int k = 0; k < 16; k++) acc += xg[k] * fc1_w[k * 16 + j];
        y1[j] = acc > 0.f ? acc : 0.1f * acc;
    }
    float y2[8];
#pragma unroll
    for (int j = 0; j < 8; j++) {
        float acc = fc2_b[j];
#pragma unroll
        for (int k = 0; k < 16; k++) acc += y1[k] * fc2_w[k * 8 + j];
        y2[j] = acc > 0.f ? acc : 0.1f * acc;
    }
    float o = out_b[0];
#pragma unroll
    for (int k = 0; k < 8; k++) o += y2[k] * out_w[k];
    out[g] = 1.f / (1.f + expf(-o));
}

// ---------------- host launch (exact round-5 structure) --------------------------
extern "C" void kernel_launch(void* const* d_in, const int* in_sizes, int n_in,
                              void* d_out, int out_size) {
    const float* x      = (const float*)d_in[0];
    const float* W1     = (const float*)d_in[1];
    const float* b1     = (const float*)d_in[2];
    const float* W2     = (const float*)d_in[3];
    const float* b2     = (const float*)d_in[4];
    const float* W3     = (const float*)d_in[5];
    const float* b3     = (const float*)d_in[6];
    const float* g1     = (const float*)d_in[7];
    const float* be1    = (const float*)d_in[8];
    const float* g2     = (const float*)d_in[9];
    const float* be2    = (const float*)d_in[10];
    const float* g3     = (const float*)d_in[11];
    const float* be3    = (const float*)d_in[12];
    const float* attn_w = (const float*)d_in[13];
    const float* attn_b = (const float*)d_in[14];
    const float* fc1_w  = (const float*)d_in[15];
    const float* fc1_b  = (const float*)d_in[16];
    const float* fc2_w  = (const float*)d_in[17];
    const float* fc2_b  = (const float*)d_in[18];
    const float* out_w  = (const float*)d_in[19];
    const float* out_b  = (const float*)d_in[20];
    const int*   ei     = (const int*)d_in[21];
    const int*   batch  = (const int*)d_in[22];

    const int* src = ei;
    const int* dst = ei + Ee;
    float* out = (float*)d_out;

    void *pA = nullptr, *pB = nullptr, *pS = nullptr;
    cudaGetSymbolAddress(&pA, g_bufA);
    cudaGetSymbolAddress(&pB, g_bufB);
    cudaGetSymbolAddress(&pS, g_stats);
    float* bufA = (float*)pA;
    float* bufB = (float*)pB;
    float* st0 = (float*)pS;
    float* st1 = st0 + 128;
    float* st2 = st0 + 256;

    static cudaStream_t sB = nullptr;
    static cudaEvent_t evFork = nullptr, evJoin = nullptr;
    if (sB == nullptr) {
        cudaStreamCreateWithFlags(&sB, cudaStreamNonBlocking);
        cudaEventCreateWithFlags(&evFork, cudaEventDisableTiming);
        cudaEventCreateWithFlags(&evJoin, cudaEventDisableTiming);
    }

    const int gemm_grid = (Nn + 127) / 128;   // 782
    const int gather_grid = 1184;             // 148 SMs * 8 blocks

    // ---- prefix: degree + dis ----
    k_zero<<<(Nn + 255) / 256, 256>>>();
    k_hist<<<(Ee + 255) / 256, 256>>>(dst);
    k_dis<<<(Nn + 255) / 256, 256>>>();
    cudaEventRecord(evFork, 0);

    // ---- branch B: GEMM1 (needs only dis), overlaps scan/fill ----
    cudaStreamWaitEvent(sB, evFork, 0);
    k_gemm<128, 64, false><<<gemm_grid, 128, 0, sB>>>(x, W1, nullptr, nullptr, nullptr, bufA);
    cudaEventRecord(evJoin, sB);

    // ---- branch A (main stream): CSR scan + fill ----
    k_scan1<<<SCAN_NB, 512>>>();
    k_scan2<<<1, 256>>>();
    k_scan3<<<SCAN_NB, 512>>>();
    k_fill<<<(Ee + 255) / 256, 256>>>(src, dst);

    // ---- join: gather needs CSR + GEMM1 output ----
    cudaStreamWaitEvent(0, evJoin, 0);
    k_gather64<<<gather_grid, 256>>>(bufA, b1, bufB, st0);

    // Layer 2: 64 -> 32 (BN1 + lrelu fused into GEMM load)
    k_gemm<64, 32, true><<<gemm_grid, 128>>>(bufB, W2, st0, g1, be1, bufA);
    k_gather<32><<<gather_grid, 256>>>(bufA, b2, bufB, st1);

    // Layer 3: 32 -> 16 (BN2 + lrelu fused into GEMM load)
    k_gemm<32, 16, true><<<gemm_grid, 128>>>(bufB, W3, st1, g2, be2, bufA);
    k_gather<16><<<gather_grid, 256>>>(bufA, b3, bufB, st2);

    // Pool (BN3 + lrelu fused) + head
    k_pool<<<Gg, 256>>>(bufB, batch, st2, g3, be3);
    k_head<<<1, 64>>>(attn_w, attn_b, fc1_w, fc1_b, fc2_w, fc2_b, out_w, out_b, out);
}